// round 1
// baseline (speedup 1.0000x reference)
#include <cuda_runtime.h>
#include <cstdint>
#include <cstddef>

#define BB   256
#define CH   64
#define HH   28
#define WW   28
#define HW   784
#define H2   14
#define W2   14
#define P2   196
#define NC   128

static __constant__ float cH0[13] = {
    -0.0017578f, 0.0f, 0.0222656f, -0.046875f, -0.0482422f, 0.296875f,
     0.5554688f, 0.296875f, -0.0482422f, -0.046875f, 0.0222656f, 0.0f, -0.0017578f};
static __constant__ float cH1[19] = {
    -7.06e-05f, 0.0f, 0.0013419f, -0.0018834f, -0.0071568f, 0.023856f,
     0.0556431f, -0.0516881f, -0.2997576f, 0.5594308f, -0.2997576f, -0.0516881f,
     0.0556431f, 0.023856f, -0.0071568f, -0.0018834f, 0.0013419f, 0.0f, -7.06e-05f};
// G0 = H1 * sgn(19)  (sgn: +1 where (i-9)%2==0, i.e. odd i)
static __constant__ float cG0[19] = {
     7.06e-05f, 0.0f, -0.0013419f, -0.0018834f, 0.0071568f, 0.023856f,
    -0.0556431f, -0.0516881f, 0.2997576f, 0.5594308f, 0.2997576f, -0.0516881f,
    -0.0556431f, 0.023856f, 0.0071568f, -0.0018834f, -0.0013419f, 0.0f, 7.06e-05f};
// G1 = -(H0 * sgn(13)) (sgn: +1 where i even)
static __constant__ float cG1[13] = {
     0.0017578f, 0.0f, -0.0222656f, -0.046875f, 0.0482422f, 0.296875f,
    -0.5554688f, 0.296875f, 0.0482422f, -0.046875f, -0.0222656f, 0.0f, 0.0017578f};

#define INV_SQRT2 0.70710678118654752440f

// scratch (allocation-free: __device__ globals)
__device__ float g_img[(size_t)BB * CH * HW];                 // transposed x2 / inverse staging
__device__ float g_ll [(size_t)BB * CH * HW];                 // ll * w_ll
__device__ float g_xh [2][(size_t)BB * CH * 6 * P2];          // [ri][b][c][s][p], reused for yh

__device__ __forceinline__ int symi(int q, int n) {
    if (q < 0)  q = -q - 1;
    if (q >= n) q = 2 * n - 1 - q;
    return q;
}

// ---------------- K0: transpose x[:, :, 64:128] -> g_img[b][c][hw] ----------------
__global__ void k_transpose_in(const float* __restrict__ x) {
    __shared__ float t[56][65];
    int b   = blockIdx.x / 14;
    int hw0 = (blockIdx.x % 14) * 56;
    #pragma unroll
    for (int it = 0; it < 14; ++it) {
        int idx = it * 256 + threadIdx.x;
        int i = idx >> 6, c = idx & 63;
        t[i][c] = x[((size_t)b * HW + hw0 + i) * NC + CH + c];
    }
    __syncthreads();
    #pragma unroll
    for (int it = 0; it < 14; ++it) {
        int idx = it * 256 + threadIdx.x;
        int i = idx % 56, c = idx / 56;
        g_img[((size_t)b * CH + c) * HW + hw0 + i] = t[i][c];
    }
}

// ---------------- K1: depthwise 3x3 conv on channels 0..63 -> out directly ----------------
__global__ void k_dwconv(const float* __restrict__ x, const float* __restrict__ w,
                         const float* __restrict__ bias, float* __restrict__ out) {
    int tid   = threadIdx.x;
    int c     = tid & 63;
    int local = tid >> 6;
    long long base = (long long)blockIdx.x * 4 + local;   // b*HW + hw
    int b  = (int)(base / HW);
    int hw = (int)(base % HW);
    int h  = hw / WW, wc = hw % WW;
    float wr[9];
    #pragma unroll
    for (int j = 0; j < 9; ++j) wr[j] = w[c * 9 + j];
    float acc = bias[c];
    #pragma unroll
    for (int dh = -1; dh <= 1; ++dh) {
        int hh = h + dh;
        if (hh < 0 || hh >= HH) continue;
        #pragma unroll
        for (int dw = -1; dw <= 1; ++dw) {
            int ww2 = wc + dw;
            if (ww2 < 0 || ww2 >= WW) continue;
            acc += x[((size_t)b * HW + hh * WW + ww2) * NC + c] * wr[(dh + 1) * 3 + (dw + 1)];
        }
    }
    out[((size_t)b * HW + hw) * NC + c] = acc;
}

// ---------------- K2: forward DTCWT per (b,c) image ----------------
__device__ __forceinline__ void q2c_store(const float* __restrict__ y, int bid,
                                          int sp, int sq, int tid) {
    if (tid < P2) {
        int h2 = tid / W2, w2 = tid % W2;
        float a  = y[(2 * h2) * WW + 2 * w2]         * INV_SQRT2;
        float bb = y[(2 * h2) * WW + 2 * w2 + 1]     * INV_SQRT2;
        float cc = y[(2 * h2 + 1) * WW + 2 * w2]     * INV_SQRT2;
        float dd = y[(2 * h2 + 1) * WW + 2 * w2 + 1] * INV_SQRT2;
        size_t bp = ((size_t)bid * 6 + sp) * P2 + tid;
        size_t bq = ((size_t)bid * 6 + sq) * P2 + tid;
        g_xh[0][bp] = a - dd;   // p real
        g_xh[1][bp] = bb + cc;  // p imag
        g_xh[0][bq] = a + dd;   // q real
        g_xh[1][bq] = bb - cc;  // q imag
    }
}

__global__ void k_fwd(const float* __restrict__ w_ll) {
    __shared__ float sA[HW], sB[HW], sC[HW];
    int bid = blockIdx.x;        // b*64 + c
    int c   = bid & 63;
    int tid = threadIdx.x;

    for (int i = tid; i < HW; i += 256) sA[i] = g_img[(size_t)bid * HW + i];
    __syncthreads();

    // row filters: lo = h0, hi = h1 (along w)
    for (int i = tid; i < HW; i += 256) {
        int h = i / WW, w = i % WW;
        const float* row = &sA[h * WW];
        float lo = 0.f, hi = 0.f;
        #pragma unroll
        for (int t = 0; t < 13; ++t) lo += row[symi(w - 6 + t, WW)] * cH0[t];
        #pragma unroll
        for (int t = 0; t < 19; ++t) hi += row[symi(w - 9 + t, WW)] * cH1[t];
        sB[i] = lo; sC[i] = hi;
    }
    __syncthreads();

    // ll = colfilt(lo,h0) * w_ll  (to global), lh = colfilt(lo,h1) -> sA
    for (int i = tid; i < HW; i += 256) {
        int h = i / WW, w = i % WW;
        float ll = 0.f;
        #pragma unroll
        for (int t = 0; t < 13; ++t) ll += sB[symi(h - 6 + t, HH) * WW + w] * cH0[t];
        g_ll[(size_t)bid * HW + i] = ll * w_ll[c * HW + i];
        float lh = 0.f;
        #pragma unroll
        for (int t = 0; t < 19; ++t) lh += sB[symi(h - 9 + t, HH) * WW + w] * cH1[t];
        sA[i] = lh;
    }
    __syncthreads();
    q2c_store(sA, bid, 0, 5, tid);   // lhp -> band0, lhq -> band5
    __syncthreads();

    // hl = colfilt(hi,h0)
    for (int i = tid; i < HW; i += 256) {
        int h = i / WW, w = i % WW;
        float v = 0.f;
        #pragma unroll
        for (int t = 0; t < 13; ++t) v += sC[symi(h - 6 + t, HH) * WW + w] * cH0[t];
        sA[i] = v;
    }
    __syncthreads();
    q2c_store(sA, bid, 2, 3, tid);   // hlp -> band2, hlq -> band3
    __syncthreads();

    // hh = colfilt(hi,h1)
    for (int i = tid; i < HW; i += 256) {
        int h = i / WW, w = i % WW;
        float v = 0.f;
        #pragma unroll
        for (int t = 0; t < 19; ++t) v += sC[symi(h - 9 + t, HH) * WW + w] * cH1[t];
        sA[i] = v;
    }
    __syncthreads();
    q2c_store(sA, bid, 1, 4, tid);   // hhp -> band1, hhq -> band4
}

// ---------------- K3: fused channel + token mixing per (b, band) ----------------
#define PITCH 197
#define SMEM_MIX_FLOATS (2*64*PITCH + 2*2048 + 2*128 + 2*5488 + 2*392)

__global__ void __launch_bounds__(256) k_mix(
    const float* __restrict__ w_lh1, const float* __restrict__ w_lh2,
    const float* __restrict__ b_lh1, const float* __restrict__ b_lh2,
    const float* __restrict__ w_t1,  const float* __restrict__ w_t2,
    const float* __restrict__ b_t1,  const float* __restrict__ b_t2) {
    extern __shared__ float sm[];
    float* Xr  = sm;                     // 64*PITCH
    float* Xi  = Xr  + 64 * PITCH;
    float* sw1 = Xi  + 64 * PITCH;       // 2048 : [ri][n][d][k]
    float* sw2 = sw1 + 2048;
    float* sb1 = sw2 + 2048;             // 128 : [ri][n][k]
    float* sb2 = sb1 + 128;
    float* st1 = sb2 + 128;              // 5488 : [ri][h2][d][k]
    float* st2 = st1 + 5488;
    float* sc1 = st2 + 5488;             // 392 : [ri][h2][k]
    float* sc2 = sc1 + 392;

    int tid = threadIdx.x;
    int b = blockIdx.x / 6, s = blockIdx.x % 6;

    for (int i = tid; i < 2048; i += 256) { sw1[i] = w_lh1[i]; sw2[i] = w_lh2[i]; }
    for (int i = tid; i < 128;  i += 256) { sb1[i] = b_lh1[i]; sb2[i] = b_lh2[i]; }
    for (int i = tid; i < 5488; i += 256) { st1[i] = w_t1[i];  st2[i] = w_t2[i]; }
    for (int i = tid; i < 392;  i += 256) { sc1[i] = b_t1[i];  sc2[i] = b_t2[i]; }
    for (int i = tid; i < 64 * P2; i += 256) {
        int c = i / P2, p = i % P2;
        size_t g = ((size_t)(b * 64 + c) * 6 + s) * P2 + p;
        Xr[c * PITCH + p] = g_xh[0][g];
        Xi[c * PITCH + p] = g_xh[1][g];
    }
    __syncthreads();

    // ---- channel mixing (block-diagonal complex, 2 layers) ----
    if (tid < P2) {
        int p = tid;
        for (int n = 0; n < 4; ++n) {
            float inr[16], ini[16];
            #pragma unroll
            for (int d = 0; d < 16; ++d) {
                inr[d] = Xr[(n * 16 + d) * PITCH + p];
                ini[d] = Xi[(n * 16 + d) * PITCH + p];
            }
            float mr[16], mi[16];
            #pragma unroll 4
            for (int k = 0; k < 16; ++k) {
                float ar = sb1[n * 16 + k], ai = sb1[64 + n * 16 + k];
                #pragma unroll
                for (int d = 0; d < 16; ++d) {
                    float wr = sw1[(n * 16 + d) * 16 + k];
                    float wi = sw1[1024 + (n * 16 + d) * 16 + k];
                    ar += inr[d] * wr - ini[d] * wi;
                    ai += inr[d] * wi + ini[d] * wr;
                }
                mr[k] = fmaxf(ar, 0.f); mi[k] = fmaxf(ai, 0.f);
            }
            #pragma unroll 4
            for (int k = 0; k < 16; ++k) {
                float ar = sb2[n * 16 + k], ai = sb2[64 + n * 16 + k];
                #pragma unroll
                for (int d = 0; d < 16; ++d) {
                    float wr = sw2[(n * 16 + d) * 16 + k];
                    float wi = sw2[1024 + (n * 16 + d) * 16 + k];
                    ar += mr[d] * wr - mi[d] * wi;
                    ai += mr[d] * wi + mi[d] * wr;
                }
                Xr[(n * 16 + k) * PITCH + p] = ar;
                Xi[(n * 16 + k) * PITCH + p] = ai;
            }
        }
    }
    __syncthreads();

    // ---- token mixing (per-h2 14x14 complex, 2 layers) ----
    for (int row = tid; row < H2 * 64; row += 256) {
        int h2 = row >> 6, c = row & 63;   // warp-uniform h2 -> broadcast weights
        float inr[14], ini[14];
        #pragma unroll
        for (int d = 0; d < 14; ++d) {
            inr[d] = Xr[c * PITCH + h2 * 14 + d];
            ini[d] = Xi[c * PITCH + h2 * 14 + d];
        }
        float mr[14], mi[14];
        #pragma unroll 2
        for (int k = 0; k < 14; ++k) {
            float ar = sc1[h2 * 14 + k], ai = sc1[196 + h2 * 14 + k];
            #pragma unroll
            for (int d = 0; d < 14; ++d) {
                float wr = st1[(h2 * 14 + d) * 14 + k];
                float wi = st1[2744 + (h2 * 14 + d) * 14 + k];
                ar += inr[d] * wr - ini[d] * wi;
                ai += inr[d] * wi + ini[d] * wr;
            }
            mr[k] = fmaxf(ar, 0.f); mi[k] = fmaxf(ai, 0.f);
        }
        size_t gbase = ((size_t)(b * 64 + c) * 6 + s) * P2 + h2 * 14;
        #pragma unroll 2
        for (int k = 0; k < 14; ++k) {
            float ar = sc2[h2 * 14 + k], ai = sc2[196 + h2 * 14 + k];
            #pragma unroll
            for (int d = 0; d < 14; ++d) {
                float wr = st2[(h2 * 14 + d) * 14 + k];
                float wi = st2[2744 + (h2 * 14 + d) * 14 + k];
                ar += mr[d] * wr - mi[d] * wi;
                ai += mr[d] * wi + mi[d] * wr;
            }
            g_xh[0][gbase + k] = ar;
            g_xh[1][gbase + k] = ai;
        }
    }
}

// ---------------- K4: inverse DTCWT per (b,c) ----------------
__global__ void k_inv() {
    __shared__ float s_ll[HW], s_lh[HW], s_hl[HW], s_hh[HW], s_lo[HW], s_hi[HW];
    int bid = blockIdx.x;
    int tid = threadIdx.x;

    for (int i = tid; i < HW; i += 256) s_ll[i] = g_ll[(size_t)bid * HW + i];
    if (tid < P2) {
        int p = tid, h2 = p / W2, w2 = p % W2;
        size_t base = (size_t)bid * 6 * P2;
        float r0 = g_xh[0][base + 0 * P2 + p], i0 = g_xh[1][base + 0 * P2 + p];
        float r1 = g_xh[0][base + 1 * P2 + p], i1 = g_xh[1][base + 1 * P2 + p];
        float r2 = g_xh[0][base + 2 * P2 + p], i2 = g_xh[1][base + 2 * P2 + p];
        float r3 = g_xh[0][base + 3 * P2 + p], i3 = g_xh[1][base + 3 * P2 + p];
        float r4 = g_xh[0][base + 4 * P2 + p], i4 = g_xh[1][base + 4 * P2 + p];
        float r5 = g_xh[0][base + 5 * P2 + p], i5 = g_xh[1][base + 5 * P2 + p];
        int o = (2 * h2) * WW + 2 * w2;
        // lh from bands (0,5)
        s_lh[o]          = (r0 + r5) * INV_SQRT2;
        s_lh[o + 1]      = (i0 + i5) * INV_SQRT2;
        s_lh[o + WW]     = (i0 - i5) * INV_SQRT2;
        s_lh[o + WW + 1] = (r5 - r0) * INV_SQRT2;
        // hl from bands (2,3)
        s_hl[o]          = (r2 + r3) * INV_SQRT2;
        s_hl[o + 1]      = (i2 + i3) * INV_SQRT2;
        s_hl[o + WW]     = (i2 - i3) * INV_SQRT2;
        s_hl[o + WW + 1] = (r3 - r2) * INV_SQRT2;
        // hh from bands (1,4)
        s_hh[o]          = (r1 + r4) * INV_SQRT2;
        s_hh[o + 1]      = (i1 + i4) * INV_SQRT2;
        s_hh[o + WW]     = (i1 - i4) * INV_SQRT2;
        s_hh[o + WW + 1] = (r4 - r1) * INV_SQRT2;
    }
    __syncthreads();

    // column filters: lo = g0(ll) + g1(lh), hi = g0(hl) + g1(hh)
    for (int i = tid; i < HW; i += 256) {
        int h = i / WW, w = i % WW;
        float lo = 0.f, hi = 0.f;
        #pragma unroll
        for (int t = 0; t < 19; ++t) lo += s_ll[symi(h - 9 + t, HH) * WW + w] * cG0[t];
        #pragma unroll
        for (int t = 0; t < 13; ++t) lo += s_lh[symi(h - 6 + t, HH) * WW + w] * cG1[t];
        #pragma unroll
        for (int t = 0; t < 19; ++t) hi += s_hl[symi(h - 9 + t, HH) * WW + w] * cG0[t];
        #pragma unroll
        for (int t = 0; t < 13; ++t) hi += s_hh[symi(h - 6 + t, HH) * WW + w] * cG1[t];
        s_lo[i] = lo; s_hi[i] = hi;
    }
    __syncthreads();

    // row filters: out = g0(lo) + g1(hi)  -> staged to g_img for the final transpose
    for (int i = tid; i < HW; i += 256) {
        int h = i / WW, w = i % WW;
        const float* rlo = &s_lo[h * WW];
        const float* rhi = &s_hi[h * WW];
        float v = 0.f;
        #pragma unroll
        for (int t = 0; t < 19; ++t) v += rlo[symi(w - 9 + t, WW)] * cG0[t];
        #pragma unroll
        for (int t = 0; t < 13; ++t) v += rhi[symi(w - 6 + t, WW)] * cG1[t];
        g_img[(size_t)bid * HW + i] = v;
    }
}

// ---------------- K5: transpose g_img -> out[:, :, 64:128] ----------------
__global__ void k_transpose_out(float* __restrict__ out) {
    __shared__ float t[56][65];
    int b   = blockIdx.x / 14;
    int hw0 = (blockIdx.x % 14) * 56;
    #pragma unroll
    for (int it = 0; it < 14; ++it) {
        int idx = it * 256 + threadIdx.x;
        int i = idx % 56, c = idx / 56;
        t[i][c] = g_img[((size_t)b * CH + c) * HW + hw0 + i];
    }
    __syncthreads();
    #pragma unroll
    for (int it = 0; it < 14; ++it) {
        int idx = it * 256 + threadIdx.x;
        int i = idx >> 6, c = idx & 63;
        out[((size_t)b * HW + hw0 + i) * NC + CH + c] = t[i][c];
    }
}

extern "C" void kernel_launch(void* const* d_in, const int* in_sizes, int n_in,
                              void* d_out, int out_size) {
    const float* x      = (const float*)d_in[0];
    const float* conv_w = (const float*)d_in[1];
    const float* conv_b = (const float*)d_in[2];
    const float* w_ll   = (const float*)d_in[3];
    const float* w_lh1  = (const float*)d_in[4];
    const float* w_lh2  = (const float*)d_in[5];
    const float* b_lh1  = (const float*)d_in[6];
    const float* b_lh2  = (const float*)d_in[7];
    const float* w_t1   = (const float*)d_in[8];
    const float* w_t2   = (const float*)d_in[9];
    const float* b_t1   = (const float*)d_in[10];
    const float* b_t2   = (const float*)d_in[11];
    float* out = (float*)d_out;

    cudaFuncSetAttribute(k_mix, cudaFuncAttributeMaxDynamicSharedMemorySize,
                         SMEM_MIX_FLOATS * (int)sizeof(float));

    k_transpose_in<<<BB * 14, 256>>>(x);
    k_dwconv<<<BB * HW / 4, 256>>>(x, conv_w, conv_b, out);
    k_fwd<<<BB * CH, 256>>>(w_ll);
    k_mix<<<BB * 6, 256, SMEM_MIX_FLOATS * sizeof(float)>>>(
        w_lh1, w_lh2, b_lh1, b_lh2, w_t1, w_t2, b_t1, b_t2);
    k_inv<<<BB * CH, 256>>>();
    k_transpose_out<<<BB * 14, 256>>>(out);
}

// round 2
// speedup vs baseline: 1.3189x; 1.3189x over previous
#include <cuda_runtime.h>
#include <cstdint>
#include <cstddef>

#define BB   256
#define CH   64
#define HH   28
#define WW   28
#define HW   784
#define H2   14
#define W2   14
#define P2   196
#define NC   128

static __constant__ float cH0[13] = {
    -0.0017578f, 0.0f, 0.0222656f, -0.046875f, -0.0482422f, 0.296875f,
     0.5554688f, 0.296875f, -0.0482422f, -0.046875f, 0.0222656f, 0.0f, -0.0017578f};
static __constant__ float cH1[19] = {
    -7.06e-05f, 0.0f, 0.0013419f, -0.0018834f, -0.0071568f, 0.023856f,
     0.0556431f, -0.0516881f, -0.2997576f, 0.5594308f, -0.2997576f, -0.0516881f,
     0.0556431f, 0.023856f, -0.0071568f, -0.0018834f, 0.0013419f, 0.0f, -7.06e-05f};
static __constant__ float cG0[19] = {
     7.06e-05f, 0.0f, -0.0013419f, -0.0018834f, 0.0071568f, 0.023856f,
    -0.0556431f, -0.0516881f, 0.2997576f, 0.5594308f, 0.2997576f, -0.0516881f,
    -0.0556431f, 0.023856f, 0.0071568f, -0.0018834f, -0.0013419f, 0.0f, 7.06e-05f};
static __constant__ float cG1[13] = {
     0.0017578f, 0.0f, -0.0222656f, -0.046875f, 0.0482422f, 0.296875f,
    -0.5554688f, 0.296875f, 0.0482422f, -0.046875f, -0.0222656f, 0.0f, 0.0017578f};

#define INV_SQRT2 0.70710678118654752440f

// scratch (allocation-free: __device__ globals)
__device__ float g_img[(size_t)BB * CH * HW];
__device__ float g_ll [(size_t)BB * CH * HW];
__device__ float g_xh [2][(size_t)BB * CH * 6 * P2];   // [ri][b][c][s][p]

// packed complex weights: quad = {wr, wi, -wi, wr}
__device__ float4 g_cwq4[2][1024];   // [layer][(n*16+k)*16+d]
__device__ float4 g_twq4[2][2744];   // [layer][(h2*14+k)*14+d]
__device__ float2 g_cbq [2][64];     // [layer][n*16+k] = {br, bi}
__device__ float2 g_tbq [2][196];    // [layer][h2*14+k]

typedef unsigned long long u64;

__device__ __forceinline__ u64 pk2(float lo, float hi) {
    u64 r; asm("mov.b64 %0, {%1, %2};" : "=l"(r) : "f"(lo), "f"(hi)); return r;
}
__device__ __forceinline__ void upk2(u64 v, float& lo, float& hi) {
    asm("mov.b64 {%0, %1}, %2;" : "=f"(lo), "=f"(hi) : "l"(v));
}
__device__ __forceinline__ void ffma2(u64& a, u64 x, u64 w) {
    asm("fma.rn.f32x2 %0, %1, %2, %0;" : "+l"(a) : "l"(x), "l"(w));
}
__device__ __forceinline__ void lds2u64(u64& a, u64& b, unsigned addr) {
    asm volatile("ld.shared.v2.u64 {%0, %1}, [%2];" : "=l"(a), "=l"(b) : "r"(addr));
}
__device__ __forceinline__ u64 lds1u64(unsigned addr) {
    u64 r; asm volatile("ld.shared.u64 %0, [%1];" : "=l"(r) : "r"(addr)); return r;
}

__device__ __forceinline__ int symi(int q, int n) {
    if (q < 0)  q = -q - 1;
    if (q >= n) q = 2 * n - 1 - q;
    return q;
}

// ---------------- K_pack: pack complex weights into {wr,wi,-wi,wr} quads ----------------
__global__ void k_pack(const float* __restrict__ w_lh1, const float* __restrict__ w_lh2,
                       const float* __restrict__ b_lh1, const float* __restrict__ b_lh2,
                       const float* __restrict__ w_t1,  const float* __restrict__ w_t2,
                       const float* __restrict__ b_t1,  const float* __restrict__ b_t2) {
    int i = blockIdx.x * 256 + threadIdx.x;
    if (i < 1024) {
        int n = i >> 8, k = (i >> 4) & 15, d = i & 15;
        int src = n * 256 + d * 16 + k;
        float wr1 = w_lh1[src], wi1 = w_lh1[1024 + src];
        g_cwq4[0][i] = make_float4(wr1, wi1, -wi1, wr1);
        float wr2 = w_lh2[src], wi2 = w_lh2[1024 + src];
        g_cwq4[1][i] = make_float4(wr2, wi2, -wi2, wr2);
    }
    if (i < 2744) {
        int h2 = i / 196, rem = i % 196;
        int k = rem / 14, d = rem % 14;
        int src = (h2 * 14 + d) * 14 + k;
        float wr1 = w_t1[src], wi1 = w_t1[2744 + src];
        g_twq4[0][i] = make_float4(wr1, wi1, -wi1, wr1);
        float wr2 = w_t2[src], wi2 = w_t2[2744 + src];
        g_twq4[1][i] = make_float4(wr2, wi2, -wi2, wr2);
    }
    if (i < 64) {
        g_cbq[0][i] = make_float2(b_lh1[i], b_lh1[64 + i]);
        g_cbq[1][i] = make_float2(b_lh2[i], b_lh2[64 + i]);
    }
    if (i < 196) {
        g_tbq[0][i] = make_float2(b_t1[i], b_t1[196 + i]);
        g_tbq[1][i] = make_float2(b_t2[i], b_t2[196 + i]);
    }
}

// ---------------- K0: transpose x[:, :, 64:128] -> g_img[b][c][hw] ----------------
__global__ void k_transpose_in(const float* __restrict__ x) {
    __shared__ float t[56][65];
    int b   = blockIdx.x / 14;
    int hw0 = (blockIdx.x % 14) * 56;
    #pragma unroll
    for (int it = 0; it < 14; ++it) {
        int idx = it * 256 + threadIdx.x;
        int i = idx >> 6, c = idx & 63;
        t[i][c] = x[((size_t)b * HW + hw0 + i) * NC + CH + c];
    }
    __syncthreads();
    #pragma unroll
    for (int it = 0; it < 14; ++it) {
        int idx = it * 256 + threadIdx.x;
        int i = idx % 56, c = idx / 56;
        g_img[((size_t)b * CH + c) * HW + hw0 + i] = t[i][c];
    }
}

// ---------------- K1: depthwise 3x3 conv on channels 0..63 -> out ----------------
__global__ void k_dwconv(const float* __restrict__ x, const float* __restrict__ w,
                         const float* __restrict__ bias, float* __restrict__ out) {
    int tid   = threadIdx.x;
    int c     = tid & 63;
    int local = tid >> 6;
    long long base = (long long)blockIdx.x * 4 + local;
    int b  = (int)(base / HW);
    int hw = (int)(base % HW);
    int h  = hw / WW, wc = hw % WW;
    float wr[9];
    #pragma unroll
    for (int j = 0; j < 9; ++j) wr[j] = w[c * 9 + j];
    float acc = bias[c];
    #pragma unroll
    for (int dh = -1; dh <= 1; ++dh) {
        int hh = h + dh;
        if (hh < 0 || hh >= HH) continue;
        #pragma unroll
        for (int dw = -1; dw <= 1; ++dw) {
            int ww2 = wc + dw;
            if (ww2 < 0 || ww2 >= WW) continue;
            acc += x[((size_t)b * HW + hh * WW + ww2) * NC + c] * wr[(dh + 1) * 3 + (dw + 1)];
        }
    }
    out[((size_t)b * HW + hw) * NC + c] = acc;
}

// ---------------- K2: forward DTCWT per (b,c) image ----------------
__device__ __forceinline__ void q2c_store(const float* __restrict__ y, int bid,
                                          int sp, int sq, int tid) {
    if (tid < P2) {
        int h2 = tid / W2, w2 = tid % W2;
        float a  = y[(2 * h2) * WW + 2 * w2]         * INV_SQRT2;
        float bb = y[(2 * h2) * WW + 2 * w2 + 1]     * INV_SQRT2;
        float cc = y[(2 * h2 + 1) * WW + 2 * w2]     * INV_SQRT2;
        float dd = y[(2 * h2 + 1) * WW + 2 * w2 + 1] * INV_SQRT2;
        size_t bp = ((size_t)bid * 6 + sp) * P2 + tid;
        size_t bq = ((size_t)bid * 6 + sq) * P2 + tid;
        g_xh[0][bp] = a - dd;
        g_xh[1][bp] = bb + cc;
        g_xh[0][bq] = a + dd;
        g_xh[1][bq] = bb - cc;
    }
}

__global__ void k_fwd(const float* __restrict__ w_ll) {
    __shared__ float sA[HW], sB[HW], sC[HW];
    int bid = blockIdx.x;
    int c   = bid & 63;
    int tid = threadIdx.x;

    for (int i = tid; i < HW; i += 256) sA[i] = g_img[(size_t)bid * HW + i];
    __syncthreads();

    for (int i = tid; i < HW; i += 256) {
        int h = i / WW, w = i % WW;
        const float* row = &sA[h * WW];
        float lo = 0.f, hi = 0.f;
        #pragma unroll
        for (int t = 0; t < 13; ++t) lo += row[symi(w - 6 + t, WW)] * cH0[t];
        #pragma unroll
        for (int t = 0; t < 19; ++t) hi += row[symi(w - 9 + t, WW)] * cH1[t];
        sB[i] = lo; sC[i] = hi;
    }
    __syncthreads();

    for (int i = tid; i < HW; i += 256) {
        int h = i / WW, w = i % WW;
        float ll = 0.f;
        #pragma unroll
        for (int t = 0; t < 13; ++t) ll += sB[symi(h - 6 + t, HH) * WW + w] * cH0[t];
        g_ll[(size_t)bid * HW + i] = ll * w_ll[c * HW + i];
        float lh = 0.f;
        #pragma unroll
        for (int t = 0; t < 19; ++t) lh += sB[symi(h - 9 + t, HH) * WW + w] * cH1[t];
        sA[i] = lh;
    }
    __syncthreads();
    q2c_store(sA, bid, 0, 5, tid);
    __syncthreads();

    for (int i = tid; i < HW; i += 256) {
        int h = i / WW, w = i % WW;
        float v = 0.f;
        #pragma unroll
        for (int t = 0; t < 13; ++t) v += sC[symi(h - 6 + t, HH) * WW + w] * cH0[t];
        sA[i] = v;
    }
    __syncthreads();
    q2c_store(sA, bid, 2, 3, tid);
    __syncthreads();

    for (int i = tid; i < HW; i += 256) {
        int h = i / WW, w = i % WW;
        float v = 0.f;
        #pragma unroll
        for (int t = 0; t < 19; ++t) v += sC[symi(h - 9 + t, HH) * WW + w] * cH1[t];
        sA[i] = v;
    }
    __syncthreads();
    q2c_store(sA, bid, 1, 4, tid);
}

// ---------------- K3a: channel mixing (block-diag complex, 2 layers, f32x2) ----------------
// grid 1176 x 256 threads; thread = one (b,s,p) position; in-place on g_xh
__global__ void __launch_bounds__(256, 2) k_chmix() {
    __shared__ float4 scw[2][1024];
    __shared__ float2 scb[2][64];
    int tid = threadIdx.x;
    #pragma unroll
    for (int i = 0; i < 4; ++i) {
        scw[0][tid + 256 * i] = g_cwq4[0][tid + 256 * i];
        scw[1][tid + 256 * i] = g_cwq4[1][tid + 256 * i];
    }
    if (tid < 64) { scb[0][tid] = g_cbq[0][tid]; scb[1][tid] = g_cbq[1][tid]; }
    __syncthreads();

    unsigned w0a = (unsigned)__cvta_generic_to_shared(&scw[0][0]);
    unsigned w1a = (unsigned)__cvta_generic_to_shared(&scw[1][0]);
    unsigned b0a = (unsigned)__cvta_generic_to_shared(&scb[0][0]);
    unsigned b1a = (unsigned)__cvta_generic_to_shared(&scb[1][0]);

    int item = blockIdx.x * 256 + tid;
    int b = item / 1176, rem = item - b * 1176;
    int s = rem / 196, p = rem - s * 196;
    float* Xr = g_xh[0];
    float* Xi = g_xh[1];
    size_t base = ((size_t)b * 384 + s) * 196 + p;   // +c*1176 per channel

    for (int n = 0; n < 4; ++n) {
        u64 Xp[16], Xq[16];
        #pragma unroll
        for (int d = 0; d < 16; ++d) {
            float r = Xr[base + (size_t)(n * 16 + d) * 1176];
            float m = Xi[base + (size_t)(n * 16 + d) * 1176];
            Xp[d] = pk2(r, r);
            Xq[d] = pk2(m, m);
        }
        float mr[16], mi[16];
        #pragma unroll
        for (int k = 0; k < 16; ++k) {
            u64 A = lds1u64(b0a + (unsigned)(n * 16 + k) * 8);
            unsigned wa = w0a + (unsigned)((n * 16 + k) * 16) * 16;
            #pragma unroll
            for (int d = 0; d < 16; ++d) {
                u64 W0, W1; lds2u64(W0, W1, wa + d * 16);
                ffma2(A, Xp[d], W0);
                ffma2(A, Xq[d], W1);
            }
            float ar, ai; upk2(A, ar, ai);
            mr[k] = fmaxf(ar, 0.f);
            mi[k] = fmaxf(ai, 0.f);
        }
        #pragma unroll
        for (int d = 0; d < 16; ++d) { Xp[d] = pk2(mr[d], mr[d]); Xq[d] = pk2(mi[d], mi[d]); }
        #pragma unroll
        for (int k = 0; k < 16; ++k) {
            u64 A = lds1u64(b1a + (unsigned)(n * 16 + k) * 8);
            unsigned wa = w1a + (unsigned)((n * 16 + k) * 16) * 16;
            #pragma unroll
            for (int d = 0; d < 16; ++d) {
                u64 W0, W1; lds2u64(W0, W1, wa + d * 16);
                ffma2(A, Xp[d], W0);
                ffma2(A, Xq[d], W1);
            }
            float ar, ai; upk2(A, ar, ai);
            Xr[base + (size_t)(n * 16 + k) * 1176] = ar;
            Xi[base + (size_t)(n * 16 + k) * 1176] = ai;
        }
    }
}

// ---------------- K3b: token mixing (per-h2 14x14 complex, 2 layers, f32x2) ----------------
// grid 256*14*3, block 128; thread = one (b,s,c,h2) row; in-place on g_xh
__global__ void __launch_bounds__(128, 4) k_token() {
    __shared__ float4 stw[2][196];
    __shared__ float2 stb[2][14];
    int tid = threadIdx.x;
    int b  = blockIdx.x / 42;
    int r  = blockIdx.x % 42;
    int h2 = r / 3;
    int gs = r % 3;
    for (int i = tid; i < 196; i += 128) {
        stw[0][i] = g_twq4[0][h2 * 196 + i];
        stw[1][i] = g_twq4[1][h2 * 196 + i];
    }
    if (tid < 14) { stb[0][tid] = g_tbq[0][h2 * 14 + tid]; stb[1][tid] = g_tbq[1][h2 * 14 + tid]; }
    __syncthreads();

    unsigned w0a = (unsigned)__cvta_generic_to_shared(&stw[0][0]);
    unsigned w1a = (unsigned)__cvta_generic_to_shared(&stw[1][0]);
    unsigned b0a = (unsigned)__cvta_generic_to_shared(&stb[0][0]);
    unsigned b1a = (unsigned)__cvta_generic_to_shared(&stb[1][0]);

    int s = gs * 2 + (tid >> 6);
    int c = tid & 63;
    size_t base = ((size_t)(b * 64 + c) * 6 + s) * 196 + h2 * 14;
    float2* Rp = (float2*)(g_xh[0] + base);
    float2* Ip = (float2*)(g_xh[1] + base);

    u64 Xp[14], Xq[14];
    #pragma unroll
    for (int j = 0; j < 7; ++j) {
        float2 v = Rp[j];
        Xp[2 * j]     = pk2(v.x, v.x);
        Xp[2 * j + 1] = pk2(v.y, v.y);
        float2 w = Ip[j];
        Xq[2 * j]     = pk2(w.x, w.x);
        Xq[2 * j + 1] = pk2(w.y, w.y);
    }
    float mr[14], mi[14];
    #pragma unroll
    for (int k = 0; k < 14; ++k) {
        u64 A = lds1u64(b0a + (unsigned)k * 8);
        unsigned wa = w0a + (unsigned)(k * 14) * 16;
        #pragma unroll
        for (int d = 0; d < 14; ++d) {
            u64 W0, W1; lds2u64(W0, W1, wa + d * 16);
            ffma2(A, Xp[d], W0);
            ffma2(A, Xq[d], W1);
        }
        float ar, ai; upk2(A, ar, ai);
        mr[k] = fmaxf(ar, 0.f);
        mi[k] = fmaxf(ai, 0.f);
    }
    #pragma unroll
    for (int d = 0; d < 14; ++d) { Xp[d] = pk2(mr[d], mr[d]); Xq[d] = pk2(mi[d], mi[d]); }
    float outr[14], outi[14];
    #pragma unroll
    for (int k = 0; k < 14; ++k) {
        u64 A = lds1u64(b1a + (unsigned)k * 8);
        unsigned wa = w1a + (unsigned)(k * 14) * 16;
        #pragma unroll
        for (int d = 0; d < 14; ++d) {
            u64 W0, W1; lds2u64(W0, W1, wa + d * 16);
            ffma2(A, Xp[d], W0);
            ffma2(A, Xq[d], W1);
        }
        upk2(A, outr[k], outi[k]);
    }
    #pragma unroll
    for (int j = 0; j < 7; ++j) {
        Rp[j] = make_float2(outr[2 * j], outr[2 * j + 1]);
        Ip[j] = make_float2(outi[2 * j], outi[2 * j + 1]);
    }
}

// ---------------- K4: inverse DTCWT per (b,c) ----------------
__global__ void k_inv() {
    __shared__ float s_ll[HW], s_lh[HW], s_hl[HW], s_hh[HW], s_lo[HW], s_hi[HW];
    int bid = blockIdx.x;
    int tid = threadIdx.x;

    for (int i = tid; i < HW; i += 256) s_ll[i] = g_ll[(size_t)bid * HW + i];
    if (tid < P2) {
        int p = tid, h2 = p / W2, w2 = p % W2;
        size_t base = (size_t)bid * 6 * P2;
        float r0 = g_xh[0][base + 0 * P2 + p], i0 = g_xh[1][base + 0 * P2 + p];
        float r1 = g_xh[0][base + 1 * P2 + p], i1 = g_xh[1][base + 1 * P2 + p];
        float r2 = g_xh[0][base + 2 * P2 + p], i2 = g_xh[1][base + 2 * P2 + p];
        float r3 = g_xh[0][base + 3 * P2 + p], i3 = g_xh[1][base + 3 * P2 + p];
        float r4 = g_xh[0][base + 4 * P2 + p], i4 = g_xh[1][base + 4 * P2 + p];
        float r5 = g_xh[0][base + 5 * P2 + p], i5 = g_xh[1][base + 5 * P2 + p];
        int o = (2 * h2) * WW + 2 * w2;
        s_lh[o]          = (r0 + r5) * INV_SQRT2;
        s_lh[o + 1]      = (i0 + i5) * INV_SQRT2;
        s_lh[o + WW]     = (i0 - i5) * INV_SQRT2;
        s_lh[o + WW + 1] = (r5 - r0) * INV_SQRT2;
        s_hl[o]          = (r2 + r3) * INV_SQRT2;
        s_hl[o + 1]      = (i2 + i3) * INV_SQRT2;
        s_hl[o + WW]     = (i2 - i3) * INV_SQRT2;
        s_hl[o + WW + 1] = (r3 - r2) * INV_SQRT2;
        s_hh[o]          = (r1 + r4) * INV_SQRT2;
        s_hh[o + 1]      = (i1 + i4) * INV_SQRT2;
        s_hh[o + WW]     = (i1 - i4) * INV_SQRT2;
        s_hh[o + WW + 1] = (r4 - r1) * INV_SQRT2;
    }
    __syncthreads();

    for (int i = tid; i < HW; i += 256) {
        int h = i / WW, w = i % WW;
        float lo = 0.f, hi = 0.f;
        #pragma unroll
        for (int t = 0; t < 19; ++t) lo += s_ll[symi(h - 9 + t, HH) * WW + w] * cG0[t];
        #pragma unroll
        for (int t = 0; t < 13; ++t) lo += s_lh[symi(h - 6 + t, HH) * WW + w] * cG1[t];
        #pragma unroll
        for (int t = 0; t < 19; ++t) hi += s_hl[symi(h - 9 + t, HH) * WW + w] * cG0[t];
        #pragma unroll
        for (int t = 0; t < 13; ++t) hi += s_hh[symi(h - 6 + t, HH) * WW + w] * cG1[t];
        s_lo[i] = lo; s_hi[i] = hi;
    }
    __syncthreads();

    for (int i = tid; i < HW; i += 256) {
        int h = i / WW, w = i % WW;
        const float* rlo = &s_lo[h * WW];
        const float* rhi = &s_hi[h * WW];
        float v = 0.f;
        #pragma unroll
        for (int t = 0; t < 19; ++t) v += rlo[symi(w - 9 + t, WW)] * cG0[t];
        #pragma unroll
        for (int t = 0; t < 13; ++t) v += rhi[symi(w - 6 + t, WW)] * cG1[t];
        g_img[(size_t)bid * HW + i] = v;
    }
}

// ---------------- K5: transpose g_img -> out[:, :, 64:128] ----------------
__global__ void k_transpose_out(float* __restrict__ out) {
    __shared__ float t[56][65];
    int b   = blockIdx.x / 14;
    int hw0 = (blockIdx.x % 14) * 56;
    #pragma unroll
    for (int it = 0; it < 14; ++it) {
        int idx = it * 256 + threadIdx.x;
        int i = idx % 56, c = idx / 56;
        t[i][c] = g_img[((size_t)b * CH + c) * HW + hw0 + i];
    }
    __syncthreads();
    #pragma unroll
    for (int it = 0; it < 14; ++it) {
        int idx = it * 256 + threadIdx.x;
        int i = idx >> 6, c = idx & 63;
        out[((size_t)b * HW + hw0 + i) * NC + CH + c] = t[i][c];
    }
}

extern "C" void kernel_launch(void* const* d_in, const int* in_sizes, int n_in,
                              void* d_out, int out_size) {
    const float* x      = (const float*)d_in[0];
    const float* conv_w = (const float*)d_in[1];
    const float* conv_b = (const float*)d_in[2];
    const float* w_ll   = (const float*)d_in[3];
    const float* w_lh1  = (const float*)d_in[4];
    const float* w_lh2  = (const float*)d_in[5];
    const float* b_lh1  = (const float*)d_in[6];
    const float* b_lh2  = (const float*)d_in[7];
    const float* w_t1   = (const float*)d_in[8];
    const float* w_t2   = (const float*)d_in[9];
    const float* b_t1   = (const float*)d_in[10];
    const float* b_t2   = (const float*)d_in[11];
    float* out = (float*)d_out;

    k_pack<<<11, 256>>>(w_lh1, w_lh2, b_lh1, b_lh2, w_t1, w_t2, b_t1, b_t2);
    k_transpose_in<<<BB * 14, 256>>>(x);
    k_dwconv<<<BB * HW / 4, 256>>>(x, conv_w, conv_b, out);
    k_fwd<<<BB * CH, 256>>>(w_ll);
    k_chmix<<<1176, 256>>>();
    k_token<<<BB * 14 * 3, 128>>>();
    k_inv<<<BB * CH, 256>>>();
    k_transpose_out<<<BB * 14, 256>>>(out);
}

// round 4
// speedup vs baseline: 1.3947x; 1.0575x over previous
#include <cuda_runtime.h>
#include <cstdint>
#include <cstddef>

#define BB   256
#define CH   64
#define HH   28
#define WW   28
#define HW   784
#define H2   14
#define W2   14
#define P2   196
#define NC   128

// filter taps: __device__ constexpr -> folded to immediates in unrolled loops
__device__ constexpr float kH0[13] = {
    -0.0017578f, 0.0f, 0.0222656f, -0.046875f, -0.0482422f, 0.296875f,
     0.5554688f, 0.296875f, -0.0482422f, -0.046875f, 0.0222656f, 0.0f, -0.0017578f};
__device__ constexpr float kH1[19] = {
    -7.06e-05f, 0.0f, 0.0013419f, -0.0018834f, -0.0071568f, 0.023856f,
     0.0556431f, -0.0516881f, -0.2997576f, 0.5594308f, -0.2997576f, -0.0516881f,
     0.0556431f, 0.023856f, -0.0071568f, -0.0018834f, 0.0013419f, 0.0f, -7.06e-05f};
__device__ constexpr float kG0[19] = {
     7.06e-05f, 0.0f, -0.0013419f, -0.0018834f, 0.0071568f, 0.023856f,
    -0.0556431f, -0.0516881f, 0.2997576f, 0.5594308f, 0.2997576f, -0.0516881f,
    -0.0556431f, 0.023856f, 0.0071568f, -0.0018834f, -0.0013419f, 0.0f, 7.06e-05f};
__device__ constexpr float kG1[13] = {
     0.0017578f, 0.0f, -0.0222656f, -0.046875f, 0.0482422f, 0.296875f,
    -0.5554688f, 0.296875f, 0.0482422f, -0.046875f, -0.0222656f, 0.0f, 0.0017578f};

#define INV_SQRT2 0.70710678118654752440f
#define RPITCH 48          // row-padded pitch: w index -9..36 -> 0..45
#define CROWS  46          // col-padded rows:  h index -9..36 -> 0..45

// scratch (allocation-free: __device__ globals)
__device__ float g_img[(size_t)BB * CH * HW];
__device__ float g_ll [(size_t)BB * CH * HW];
__device__ float g_xh [2][(size_t)BB * CH * 6 * P2];   // [ri][b][c][s][p]

// packed complex weights: quad = {wr, wi, -wi, wr}
__device__ float4 g_cwq4[2][1024];
__device__ float4 g_twq4[2][2744];
__device__ float2 g_cbq [2][64];
__device__ float2 g_tbq [2][196];

typedef unsigned long long u64;

__device__ __forceinline__ u64 pk2(float lo, float hi) {
    u64 r; asm("mov.b64 %0, {%1, %2};" : "=l"(r) : "f"(lo), "f"(hi)); return r;
}
__device__ __forceinline__ void upk2(u64 v, float& lo, float& hi) {
    asm("mov.b64 {%0, %1}, %2;" : "=f"(lo), "=f"(hi) : "l"(v));
}
__device__ __forceinline__ void ffma2(u64& a, u64 x, u64 w) {
    asm("fma.rn.f32x2 %0, %1, %2, %0;" : "+l"(a) : "l"(x), "l"(w));
}
__device__ __forceinline__ void lds2u64(u64& a, u64& b, unsigned addr) {
    asm volatile("ld.shared.v2.u64 {%0, %1}, [%2];" : "=l"(a), "=l"(b) : "r"(addr));
}
__device__ __forceinline__ u64 lds1u64(unsigned addr) {
    u64 r; asm volatile("ld.shared.u64 %0, [%1];" : "=l"(r) : "r"(addr)); return r;
}

// ---------------- K_pack ----------------
__global__ void k_pack(const float* __restrict__ w_lh1, const float* __restrict__ w_lh2,
                       const float* __restrict__ b_lh1, const float* __restrict__ b_lh2,
                       const float* __restrict__ w_t1,  const float* __restrict__ w_t2,
                       const float* __restrict__ b_t1,  const float* __restrict__ b_t2) {
    int i = blockIdx.x * 256 + threadIdx.x;
    if (i < 1024) {
        int n = i >> 8, k = (i >> 4) & 15, d = i & 15;
        int src = n * 256 + d * 16 + k;
        float wr1 = w_lh1[src], wi1 = w_lh1[1024 + src];
        g_cwq4[0][i] = make_float4(wr1, wi1, -wi1, wr1);
        float wr2 = w_lh2[src], wi2 = w_lh2[1024 + src];
        g_cwq4[1][i] = make_float4(wr2, wi2, -wi2, wr2);
    }
    if (i < 2744) {
        int h2 = i / 196, rem = i % 196;
        int k = rem / 14, d = rem % 14;
        int src = (h2 * 14 + d) * 14 + k;
        float wr1 = w_t1[src], wi1 = w_t1[2744 + src];
        g_twq4[0][i] = make_float4(wr1, wi1, -wi1, wr1);
        float wr2 = w_t2[src], wi2 = w_t2[2744 + src];
        g_twq4[1][i] = make_float4(wr2, wi2, -wi2, wr2);
    }
    if (i < 64) {
        g_cbq[0][i] = make_float2(b_lh1[i], b_lh1[64 + i]);
        g_cbq[1][i] = make_float2(b_lh2[i], b_lh2[64 + i]);
    }
    if (i < 196) {
        g_tbq[0][i] = make_float2(b_t1[i], b_t1[196 + i]);
        g_tbq[1][i] = make_float2(b_t2[i], b_t2[196 + i]);
    }
}

// ---------------- K0: transpose x[:, :, 64:128] -> g_img[b][c][hw] ----------------
__global__ void k_transpose_in(const float* __restrict__ x) {
    __shared__ float t[56][65];
    int b   = blockIdx.x / 14;
    int hw0 = (blockIdx.x % 14) * 56;
    #pragma unroll
    for (int it = 0; it < 14; ++it) {
        int idx = it * 256 + threadIdx.x;
        int i = idx >> 6, c = idx & 63;
        t[i][c] = x[((size_t)b * HW + hw0 + i) * NC + CH + c];
    }
    __syncthreads();
    #pragma unroll
    for (int it = 0; it < 14; ++it) {
        int idx = it * 256 + threadIdx.x;
        int i = idx % 56, c = idx / 56;
        g_img[((size_t)b * CH + c) * HW + hw0 + i] = t[i][c];
    }
}

// ---------------- K1: depthwise 3x3 conv ----------------
__global__ void k_dwconv(const float* __restrict__ x, const float* __restrict__ w,
                         const float* __restrict__ bias, float* __restrict__ out) {
    int tid   = threadIdx.x;
    int c     = tid & 63;
    int local = tid >> 6;
    long long base = (long long)blockIdx.x * 4 + local;
    int b  = (int)(base / HW);
    int hw = (int)(base % HW);
    int h  = hw / WW, wc = hw % WW;
    float wr[9];
    #pragma unroll
    for (int j = 0; j < 9; ++j) wr[j] = w[c * 9 + j];
    float acc = bias[c];
    #pragma unroll
    for (int dh = -1; dh <= 1; ++dh) {
        int hh = h + dh;
        if (hh < 0 || hh >= HH) continue;
        #pragma unroll
        for (int dw = -1; dw <= 1; ++dw) {
            int ww2 = wc + dw;
            if (ww2 < 0 || ww2 >= WW) continue;
            acc += x[((size_t)b * HW + hh * WW + ww2) * NC + c] * wr[(dh + 1) * 3 + (dw + 1)];
        }
    }
    out[((size_t)b * HW + hw) * NC + c] = acc;
}

// ---------------- K2: forward DTCWT (block = (28,28), padded smem) ----------------
__global__ void __launch_bounds__(784, 2) k_fwd(const float* __restrict__ w_ll) {
    __shared__ float sAp[HH][RPITCH];          // row-padded input
    __shared__ float sLo[CROWS][WW];           // col-padded lo
    __shared__ float sHi[CROWS][WW];           // col-padded hi
    __shared__ float sLH[HW], sHL[HW], sHH[HW];

    int bid = blockIdx.x;                      // b*64 + c
    int c   = bid & 63;
    int w   = threadIdx.x;
    int h   = threadIdx.y;
    int t   = h * 28 + w;

    sAp[h][9 + w] = g_img[(size_t)bid * HW + t];
    __syncthreads();
    if (w < 9) {
        sAp[h][8 - w]  = sAp[h][9 + w];        // left mirror
        sAp[h][37 + w] = sAp[h][36 - w];       // right mirror
    }
    __syncthreads();

    {   // row filters
        const float* rp = &sAp[h][w];
        float lo = 0.f, hi = 0.f;
        #pragma unroll
        for (int j = 0; j < 13; ++j) lo = fmaf(rp[3 + j], kH0[j], lo);
        #pragma unroll
        for (int j = 0; j < 19; ++j) hi = fmaf(rp[j], kH1[j], hi);
        sLo[9 + h][w] = lo;
        sHi[9 + h][w] = hi;
    }
    __syncthreads();
    if (h < 9) {
        sLo[8 - h][w]  = sLo[9 + h][w];
        sLo[37 + h][w] = sLo[36 - h][w];
        sHi[8 - h][w]  = sHi[9 + h][w];
        sHi[37 + h][w] = sHi[36 - h][w];
    }
    __syncthreads();

    {   // column filters
        const float* lp = &sLo[h][w];
        const float* hp = &sHi[h][w];
        float ll = 0.f, lh = 0.f, hl = 0.f, hh = 0.f;
        #pragma unroll
        for (int j = 0; j < 13; ++j) ll = fmaf(lp[(3 + j) * WW], kH0[j], ll);
        #pragma unroll
        for (int j = 0; j < 19; ++j) lh = fmaf(lp[j * WW], kH1[j], lh);
        #pragma unroll
        for (int j = 0; j < 13; ++j) hl = fmaf(hp[(3 + j) * WW], kH0[j], hl);
        #pragma unroll
        for (int j = 0; j < 19; ++j) hh = fmaf(hp[j * WW], kH1[j], hh);
        g_ll[(size_t)bid * HW + t] = ll * w_ll[c * HW + t];
        sLH[t] = lh; sHL[t] = hl; sHH[t] = hh;
    }
    __syncthreads();

    // q2c for 3 bands: 588 threads
    if (t < 588) {
        int band = t / 196;
        int p    = t - band * 196;
        int h2   = p / 14, w2 = p - h2 * 14;
        const float* src = (band == 0) ? sLH : (band == 1) ? sHH : sHL;
        int sp = (band == 0) ? 0 : (band == 1) ? 1 : 2;
        int sq = (band == 0) ? 5 : (band == 1) ? 4 : 3;
        int o = (2 * h2) * WW + 2 * w2;
        float a  = src[o]          * INV_SQRT2;
        float bb = src[o + 1]      * INV_SQRT2;
        float cc = src[o + WW]     * INV_SQRT2;
        float dd = src[o + WW + 1] * INV_SQRT2;
        size_t bp = ((size_t)bid * 6 + sp) * P2 + p;
        size_t bq = ((size_t)bid * 6 + sq) * P2 + p;
        g_xh[0][bp] = a - dd;
        g_xh[1][bp] = bb + cc;
        g_xh[0][bq] = a + dd;
        g_xh[1][bq] = bb - cc;
    }
}

// ---------------- K3a: channel mixing ----------------
__global__ void __launch_bounds__(256, 2) k_chmix() {
    __shared__ float4 scw[2][1024];
    __shared__ float2 scb[2][64];
    int tid = threadIdx.x;
    #pragma unroll
    for (int i = 0; i < 4; ++i) {
        scw[0][tid + 256 * i] = g_cwq4[0][tid + 256 * i];
        scw[1][tid + 256 * i] = g_cwq4[1][tid + 256 * i];
    }
    if (tid < 64) { scb[0][tid] = g_cbq[0][tid]; scb[1][tid] = g_cbq[1][tid]; }
    __syncthreads();

    unsigned w0a = (unsigned)__cvta_generic_to_shared(&scw[0][0]);
    unsigned w1a = (unsigned)__cvta_generic_to_shared(&scw[1][0]);
    unsigned b0a = (unsigned)__cvta_generic_to_shared(&scb[0][0]);
    unsigned b1a = (unsigned)__cvta_generic_to_shared(&scb[1][0]);

    int item = blockIdx.x * 256 + tid;
    int b = item / 1176, rem = item - b * 1176;
    int s = rem / 196, p = rem - s * 196;
    float* Xr = g_xh[0];
    float* Xi = g_xh[1];
    size_t base = ((size_t)b * 384 + s) * 196 + p;

    for (int n = 0; n < 4; ++n) {
        u64 Xp[16], Xq[16];
        #pragma unroll
        for (int d = 0; d < 16; ++d) {
            float r = Xr[base + (size_t)(n * 16 + d) * 1176];
            float m = Xi[base + (size_t)(n * 16 + d) * 1176];
            Xp[d] = pk2(r, r);
            Xq[d] = pk2(m, m);
        }
        float mr[16], mi[16];
        #pragma unroll
        for (int k = 0; k < 16; ++k) {
            u64 A = lds1u64(b0a + (unsigned)(n * 16 + k) * 8);
            unsigned wa = w0a + (unsigned)((n * 16 + k) * 16) * 16;
            #pragma unroll
            for (int d = 0; d < 16; ++d) {
                u64 W0, W1; lds2u64(W0, W1, wa + d * 16);
                ffma2(A, Xp[d], W0);
                ffma2(A, Xq[d], W1);
            }
            float ar, ai; upk2(A, ar, ai);
            mr[k] = fmaxf(ar, 0.f);
            mi[k] = fmaxf(ai, 0.f);
        }
        #pragma unroll
        for (int d = 0; d < 16; ++d) { Xp[d] = pk2(mr[d], mr[d]); Xq[d] = pk2(mi[d], mi[d]); }
        #pragma unroll
        for (int k = 0; k < 16; ++k) {
            u64 A = lds1u64(b1a + (unsigned)(n * 16 + k) * 8);
            unsigned wa = w1a + (unsigned)((n * 16 + k) * 16) * 16;
            #pragma unroll
            for (int d = 0; d < 16; ++d) {
                u64 W0, W1; lds2u64(W0, W1, wa + d * 16);
                ffma2(A, Xp[d], W0);
                ffma2(A, Xq[d], W1);
            }
            float ar, ai; upk2(A, ar, ai);
            Xr[base + (size_t)(n * 16 + k) * 1176] = ar;
            Xi[base + (size_t)(n * 16 + k) * 1176] = ai;
        }
    }
}

// ---------------- K3b: token mixing ----------------
__global__ void __launch_bounds__(128, 4) k_token() {
    __shared__ float4 stw[2][196];
    __shared__ float2 stb[2][14];
    int tid = threadIdx.x;
    int b  = blockIdx.x / 42;
    int r  = blockIdx.x % 42;
    int h2 = r / 3;
    int gs = r % 3;
    for (int i = tid; i < 196; i += 128) {
        stw[0][i] = g_twq4[0][h2 * 196 + i];
        stw[1][i] = g_twq4[1][h2 * 196 + i];
    }
    if (tid < 14) { stb[0][tid] = g_tbq[0][h2 * 14 + tid]; stb[1][tid] = g_tbq[1][h2 * 14 + tid]; }
    __syncthreads();

    unsigned w0a = (unsigned)__cvta_generic_to_shared(&stw[0][0]);
    unsigned w1a = (unsigned)__cvta_generic_to_shared(&stw[1][0]);
    unsigned b0a = (unsigned)__cvta_generic_to_shared(&stb[0][0]);
    unsigned b1a = (unsigned)__cvta_generic_to_shared(&stb[1][0]);

    int s = gs * 2 + (tid >> 6);
    int c = tid & 63;
    size_t base = ((size_t)(b * 64 + c) * 6 + s) * 196 + h2 * 14;
    float2* Rp = (float2*)(g_xh[0] + base);
    float2* Ip = (float2*)(g_xh[1] + base);

    u64 Xp[14], Xq[14];
    #pragma unroll
    for (int j = 0; j < 7; ++j) {
        float2 v = Rp[j];
        Xp[2 * j]     = pk2(v.x, v.x);
        Xp[2 * j + 1] = pk2(v.y, v.y);
        float2 w = Ip[j];
        Xq[2 * j]     = pk2(w.x, w.x);
        Xq[2 * j + 1] = pk2(w.y, w.y);
    }
    float mr[14], mi[14];
    #pragma unroll
    for (int k = 0; k < 14; ++k) {
        u64 A = lds1u64(b0a + (unsigned)k * 8);
        unsigned wa = w0a + (unsigned)(k * 14) * 16;
        #pragma unroll
        for (int d = 0; d < 14; ++d) {
            u64 W0, W1; lds2u64(W0, W1, wa + d * 16);
            ffma2(A, Xp[d], W0);
            ffma2(A, Xq[d], W1);
        }
        float ar, ai; upk2(A, ar, ai);
        mr[k] = fmaxf(ar, 0.f);
        mi[k] = fmaxf(ai, 0.f);
    }
    #pragma unroll
    for (int d = 0; d < 14; ++d) { Xp[d] = pk2(mr[d], mr[d]); Xq[d] = pk2(mi[d], mi[d]); }
    float outr[14], outi[14];
    #pragma unroll
    for (int k = 0; k < 14; ++k) {
        u64 A = lds1u64(b1a + (unsigned)k * 8);
        unsigned wa = w1a + (unsigned)(k * 14) * 16;
        #pragma unroll
        for (int d = 0; d < 14; ++d) {
            u64 W0, W1; lds2u64(W0, W1, wa + d * 16);
            ffma2(A, Xp[d], W0);
            ffma2(A, Xq[d], W1);
        }
        upk2(A, outr[k], outi[k]);
    }
    #pragma unroll
    for (int j = 0; j < 7; ++j) {
        Rp[j] = make_float2(outr[2 * j], outr[2 * j + 1]);
        Ip[j] = make_float2(outi[2 * j], outi[2 * j + 1]);
    }
}

// ---------------- K4: inverse DTCWT (block = (28,28), padded smem) ----------------
__global__ void __launch_bounds__(784, 2) k_inv() {
    __shared__ float sLL[CROWS][WW];
    __shared__ float sLH[CROWS][WW];
    __shared__ float sHL[CROWS][WW];
    __shared__ float sHH[CROWS][WW];
    __shared__ float sLo[HH][RPITCH];
    __shared__ float sHi[HH][RPITCH];

    int bid = blockIdx.x;
    int w   = threadIdx.x;
    int h   = threadIdx.y;
    int t   = h * 28 + w;

    sLL[9 + h][w] = g_ll[(size_t)bid * HW + t];

    if (t < 588) {   // c2q: 3 bands
        int band = t / 196;
        int p    = t - band * 196;
        int h2   = p / 14, w2 = p - h2 * 14;
        size_t base = (size_t)bid * 6 * P2;
        int sa = (band == 0) ? 0 : (band == 1) ? 2 : 1;   // lh:(0,5) hl:(2,3) hh:(1,4)
        int sb = (band == 0) ? 5 : (band == 1) ? 3 : 4;
        float ra = g_xh[0][base + sa * P2 + p], ia = g_xh[1][base + sa * P2 + p];
        float rb = g_xh[0][base + sb * P2 + p], ib = g_xh[1][base + sb * P2 + p];
        float (*dst)[WW] = (band == 0) ? sLH : (band == 1) ? sHL : sHH;
        int hr = 9 + 2 * h2, wc = 2 * w2;
        dst[hr][wc]         = (ra + rb) * INV_SQRT2;
        dst[hr][wc + 1]     = (ia + ib) * INV_SQRT2;
        dst[hr + 1][wc]     = (ia - ib) * INV_SQRT2;
        dst[hr + 1][wc + 1] = (rb - ra) * INV_SQRT2;
    }
    __syncthreads();
    if (h < 9) {
        sLL[8 - h][w]  = sLL[9 + h][w];  sLL[37 + h][w] = sLL[36 - h][w];
        sLH[8 - h][w]  = sLH[9 + h][w];  sLH[37 + h][w] = sLH[36 - h][w];
        sHL[8 - h][w]  = sHL[9 + h][w];  sHL[37 + h][w] = sHL[36 - h][w];
        sHH[8 - h][w]  = sHH[9 + h][w];  sHH[37 + h][w] = sHH[36 - h][w];
    }
    __syncthreads();

    {   // column filters: lo = g0(ll)+g1(lh), hi = g0(hl)+g1(hh)
        const float* a = &sLL[h][w];
        const float* bP = &sLH[h][w];
        const float* cP = &sHL[h][w];
        const float* dP = &sHH[h][w];
        float lo = 0.f, hi = 0.f;
        #pragma unroll
        for (int j = 0; j < 19; ++j) lo = fmaf(a[j * WW], kG0[j], lo);
        #pragma unroll
        for (int j = 0; j < 13; ++j) lo = fmaf(bP[(3 + j) * WW], kG1[j], lo);
        #pragma unroll
        for (int j = 0; j < 19; ++j) hi = fmaf(cP[j * WW], kG0[j], hi);
        #pragma unroll
        for (int j = 0; j < 13; ++j) hi = fmaf(dP[(3 + j) * WW], kG1[j], hi);
        sLo[h][9 + w] = lo;
        sHi[h][9 + w] = hi;
    }
    __syncthreads();
    if (w < 9) {
        sLo[h][8 - w]  = sLo[h][9 + w];  sLo[h][37 + w] = sLo[h][36 - w];
        sHi[h][8 - w]  = sHi[h][9 + w];  sHi[h][37 + w] = sHi[h][36 - w];
    }
    __syncthreads();

    {   // row filters
        const float* lp = &sLo[h][w];
        const float* hp = &sHi[h][w];
        float v = 0.f;
        #pragma unroll
        for (int j = 0; j < 19; ++j) v = fmaf(lp[j], kG0[j], v);
        #pragma unroll
        for (int j = 0; j < 13; ++j) v = fmaf(hp[3 + j], kG1[j], v);
        g_img[(size_t)bid * HW + t] = v;
    }
}

// ---------------- K5: transpose g_img -> out[:, :, 64:128] ----------------
__global__ void k_transpose_out(float* __restrict__ out) {
    __shared__ float t[56][65];
    int b   = blockIdx.x / 14;
    int hw0 = (blockIdx.x % 14) * 56;
    #pragma unroll
    for (int it = 0; it < 14; ++it) {
        int idx = it * 256 + threadIdx.x;
        int i = idx % 56, c = idx / 56;
        t[i][c] = g_img[((size_t)b * CH + c) * HW + hw0 + i];
    }
    __syncthreads();
    #pragma unroll
    for (int it = 0; it < 14; ++it) {
        int idx = it * 256 + threadIdx.x;
        int i = idx >> 6, c = idx & 63;
        out[((size_t)b * HW + hw0 + i) * NC + CH + c] = t[i][c];
    }
}

extern "C" void kernel_launch(void* const* d_in, const int* in_sizes, int n_in,
                              void* d_out, int out_size) {
    const float* x      = (const float*)d_in[0];
    const float* conv_w = (const float*)d_in[1];
    const float* conv_b = (const float*)d_in[2];
    const float* w_ll   = (const float*)d_in[3];
    const float* w_lh1  = (const float*)d_in[4];
    const float* w_lh2  = (const float*)d_in[5];
    const float* b_lh1  = (const float*)d_in[6];
    const float* b_lh2  = (const float*)d_in[7];
    const float* w_t1   = (const float*)d_in[8];
    const float* w_t2   = (const float*)d_in[9];
    const float* b_t1   = (const float*)d_in[10];
    const float* b_t2   = (const float*)d_in[11];
    float* out = (float*)d_out;

    dim3 blk2d(28, 28);
    k_pack<<<11, 256>>>(w_lh1, w_lh2, b_lh1, b_lh2, w_t1, w_t2, b_t1, b_t2);
    k_transpose_in<<<BB * 14, 256>>>(x);
    k_dwconv<<<BB * HW / 4, 256>>>(x, conv_w, conv_b, out);
    k_fwd<<<BB * CH, blk2d>>>(w_ll);
    k_chmix<<<1176, 256>>>();
    k_token<<<BB * 14 * 3, 128>>>();
    k_inv<<<BB * CH, blk2d>>>();
    k_transpose_out<<<BB * 14, 256>>>(out);
}

// round 5
// speedup vs baseline: 1.8864x; 1.3525x over previous
#include <cuda_runtime.h>
#include <cstdint>
#include <cstddef>

#define BB   256
#define CH   64
#define HH   28
#define WW   28
#define HW   784
#define H2   14
#define W2   14
#define P2   196
#define NC   128
#define CP   52        // padded pitch; 52 % 32 = 20 -> conflict-free LDS.128 pattern

__device__ constexpr float kH0[13] = {
    -0.0017578f, 0.0f, 0.0222656f, -0.046875f, -0.0482422f, 0.296875f,
     0.5554688f, 0.296875f, -0.0482422f, -0.046875f, 0.0222656f, 0.0f, -0.0017578f};
__device__ constexpr float kH1[19] = {
    -7.06e-05f, 0.0f, 0.0013419f, -0.0018834f, -0.0071568f, 0.023856f,
     0.0556431f, -0.0516881f, -0.2997576f, 0.5594308f, -0.2997576f, -0.0516881f,
     0.0556431f, 0.023856f, -0.0071568f, -0.0018834f, 0.0013419f, 0.0f, -7.06e-05f};
__device__ constexpr float kG0[19] = {
     7.06e-05f, 0.0f, -0.0013419f, -0.0018834f, 0.0071568f, 0.023856f,
    -0.0556431f, -0.0516881f, 0.2997576f, 0.5594308f, 0.2997576f, -0.0516881f,
    -0.0556431f, 0.023856f, 0.0071568f, -0.0018834f, -0.0013419f, 0.0f, 7.06e-05f};
__device__ constexpr float kG1[13] = {
     0.0017578f, 0.0f, -0.0222656f, -0.046875f, 0.0482422f, 0.296875f,
    -0.5554688f, 0.296875f, 0.0482422f, -0.046875f, -0.0222656f, 0.0f, 0.0017578f};

#define INV_SQRT2 0.70710678118654752440f

// scratch (allocation-free: __device__ globals)
__device__ float g_img[(size_t)BB * CH * HW];
__device__ float g_ll [(size_t)BB * CH * HW];
__device__ float g_xh [2][(size_t)BB * CH * 6 * P2];   // [ri][b][c][s][p]

// packed complex weights: quad = {wr, wi, -wi, wr}
__device__ float4 g_cwq4[2][1024];
__device__ float4 g_twq4[2][2744];
__device__ float2 g_cbq [2][64];
__device__ float2 g_tbq [2][196];

typedef unsigned long long u64;

__device__ __forceinline__ u64 pk2(float lo, float hi) {
    u64 r; asm("mov.b64 %0, {%1, %2};" : "=l"(r) : "f"(lo), "f"(hi)); return r;
}
__device__ __forceinline__ void upk2(u64 v, float& lo, float& hi) {
    asm("mov.b64 {%0, %1}, %2;" : "=f"(lo), "=f"(hi) : "l"(v));
}
__device__ __forceinline__ void ffma2(u64& a, u64 x, u64 w) {
    asm("fma.rn.f32x2 %0, %1, %2, %0;" : "+l"(a) : "l"(x), "l"(w));
}
__device__ __forceinline__ void lds2u64(u64& a, u64& b, unsigned addr) {
    asm volatile("ld.shared.v2.u64 {%0, %1}, [%2];" : "=l"(a), "=l"(b) : "r"(addr));
}
__device__ __forceinline__ u64 lds1u64(unsigned addr) {
    u64 r; asm volatile("ld.shared.u64 %0, [%1];" : "=l"(r) : "r"(addr)); return r;
}

// ---------------- K_pack ----------------
__global__ void k_pack(const float* __restrict__ w_lh1, const float* __restrict__ w_lh2,
                       const float* __restrict__ b_lh1, const float* __restrict__ b_lh2,
                       const float* __restrict__ w_t1,  const float* __restrict__ w_t2,
                       const float* __restrict__ b_t1,  const float* __restrict__ b_t2) {
    int i = blockIdx.x * 256 + threadIdx.x;
    if (i < 1024) {
        int n = i >> 8, k = (i >> 4) & 15, d = i & 15;
        int src = n * 256 + d * 16 + k;
        float wr1 = w_lh1[src], wi1 = w_lh1[1024 + src];
        g_cwq4[0][i] = make_float4(wr1, wi1, -wi1, wr1);
        float wr2 = w_lh2[src], wi2 = w_lh2[1024 + src];
        g_cwq4[1][i] = make_float4(wr2, wi2, -wi2, wr2);
    }
    if (i < 2744) {
        int h2 = i / 196, rem = i % 196;
        int k = rem / 14, d = rem % 14;
        int src = (h2 * 14 + d) * 14 + k;
        float wr1 = w_t1[src], wi1 = w_t1[2744 + src];
        g_twq4[0][i] = make_float4(wr1, wi1, -wi1, wr1);
        float wr2 = w_t2[src], wi2 = w_t2[2744 + src];
        g_twq4[1][i] = make_float4(wr2, wi2, -wi2, wr2);
    }
    if (i < 64) {
        g_cbq[0][i] = make_float2(b_lh1[i], b_lh1[64 + i]);
        g_cbq[1][i] = make_float2(b_lh2[i], b_lh2[64 + i]);
    }
    if (i < 196) {
        g_tbq[0][i] = make_float2(b_t1[i], b_t1[196 + i]);
        g_tbq[1][i] = make_float2(b_t2[i], b_t2[196 + i]);
    }
}

// ---------------- K0: transpose x[:, :, 64:128] -> g_img[b][c][hw] ----------------
__global__ void k_transpose_in(const float* __restrict__ x) {
    __shared__ float t[56][65];
    int b   = blockIdx.x / 14;
    int hw0 = (blockIdx.x % 14) * 56;
    #pragma unroll
    for (int it = 0; it < 14; ++it) {
        int idx = it * 256 + threadIdx.x;
        int i = idx >> 6, c = idx & 63;
        t[i][c] = x[((size_t)b * HW + hw0 + i) * NC + CH + c];
    }
    __syncthreads();
    #pragma unroll
    for (int it = 0; it < 14; ++it) {
        int idx = it * 256 + threadIdx.x;
        int i = idx % 56, c = idx / 56;
        g_img[((size_t)b * CH + c) * HW + hw0 + i] = t[i][c];
    }
}

// ---------------- K1: depthwise 3x3 conv ----------------
__global__ void k_dwconv(const float* __restrict__ x, const float* __restrict__ w,
                         const float* __restrict__ bias, float* __restrict__ out) {
    int tid   = threadIdx.x;
    int c     = tid & 63;
    int local = tid >> 6;
    long long base = (long long)blockIdx.x * 4 + local;
    int b  = (int)(base / HW);
    int hw = (int)(base % HW);
    int h  = hw / WW, wc = hw % WW;
    float wr[9];
    #pragma unroll
    for (int j = 0; j < 9; ++j) wr[j] = w[c * 9 + j];
    float acc = bias[c];
    #pragma unroll
    for (int dh = -1; dh <= 1; ++dh) {
        int hh = h + dh;
        if (hh < 0 || hh >= HH) continue;
        #pragma unroll
        for (int dw = -1; dw <= 1; ++dw) {
            int ww2 = wc + dw;
            if (ww2 < 0 || ww2 >= WW) continue;
            acc += x[((size_t)b * HW + hh * WW + ww2) * NC + c] * wr[(dh + 1) * 3 + (dw + 1)];
        }
    }
    out[((size_t)b * HW + hw) * NC + c] = acc;
}

// ---------------- K2: forward DTCWT (strip-of-4, register windows) ----------------
__global__ void __launch_bounds__(224, 2) k_fwd(const float* __restrict__ w_ll) {
    __shared__ float sAp [HH][CP];     // row-padded input: [h][9+w]
    __shared__ float sLoT[WW][CP];     // transposed lo: [w][9+h]
    __shared__ float sHiT[WW][CP];     // transposed hi
    __shared__ float sLH[HW], sHL[HW], sHH[HW];

    int bid = blockIdx.x;              // b*64 + c
    int c   = bid & 63;
    int tid = threadIdx.x;

    if (tid < 196) {
        float4 v = *(const float4*)(g_img + (size_t)bid * HW + tid * 4);
        int h = (tid * 4) / 28, w = (tid * 4) % 28;
        sAp[h][9 + w]     = v.x;
        sAp[h][9 + w + 1] = v.y;
        sAp[h][9 + w + 2] = v.z;
        sAp[h][9 + w + 3] = v.w;
    }
    __syncthreads();
    for (int i = tid; i < 28 * 9; i += 224) {
        int h = i / 9, j = i % 9;
        sAp[h][8 - j]  = sAp[h][9 + j];
        sAp[h][37 + j] = sAp[h][36 - j];
    }
    __syncthreads();

    // phase 1: row filters -> transposed smem
    if (tid < 196) {
        int h = tid % 28, w0 = (tid / 28) * 4;
        float X[22];
        #pragma unroll
        for (int j = 0; j < 22; ++j) X[j] = sAp[h][w0 + j];
        #pragma unroll
        for (int t = 0; t < 4; ++t) {
            float hi = 0.f, lo = 0.f;
            #pragma unroll
            for (int j = 0; j < 19; ++j) hi = fmaf(X[t + j], kH1[j], hi);
            #pragma unroll
            for (int j = 0; j < 13; ++j) lo = fmaf(X[t + 3 + j], kH0[j], lo);
            sLoT[w0 + t][9 + h] = lo;
            sHiT[w0 + t][9 + h] = hi;
        }
    }
    __syncthreads();
    for (int i = tid; i < 28 * 9; i += 224) {
        int w = i / 9, j = i % 9;
        sLoT[w][8 - j]  = sLoT[w][9 + j];  sLoT[w][37 + j] = sLoT[w][36 - j];
        sHiT[w][8 - j]  = sHiT[w][9 + j];  sHiT[w][37 + j] = sHiT[w][36 - j];
    }
    __syncthreads();

    // phase 2: column filters (contiguous in transposed layout)
    if (tid < 196) {
        int w = tid % 28, h0 = (tid / 28) * 4;
        float Y[22], Z[22];
        #pragma unroll
        for (int j = 0; j < 22; ++j) Y[j] = sLoT[w][h0 + j];
        #pragma unroll
        for (int j = 0; j < 22; ++j) Z[j] = sHiT[w][h0 + j];
        #pragma unroll
        for (int t = 0; t < 4; ++t) {
            float ll = 0.f, lh = 0.f, hl = 0.f, hh = 0.f;
            #pragma unroll
            for (int j = 0; j < 13; ++j) ll = fmaf(Y[t + 3 + j], kH0[j], ll);
            #pragma unroll
            for (int j = 0; j < 19; ++j) lh = fmaf(Y[t + j], kH1[j], lh);
            #pragma unroll
            for (int j = 0; j < 13; ++j) hl = fmaf(Z[t + 3 + j], kH0[j], hl);
            #pragma unroll
            for (int j = 0; j < 19; ++j) hh = fmaf(Z[t + j], kH1[j], hh);
            int pos = (h0 + t) * 28 + w;
            g_ll[(size_t)bid * HW + pos] = ll * w_ll[c * HW + pos];
            sLH[pos] = lh; sHL[pos] = hl; sHH[pos] = hh;
        }
    }
    __syncthreads();

    // q2c: 196 threads, 3 bands each
    if (tid < 196) {
        int p  = tid;
        int h2 = p / 14, w2 = p - h2 * 14;
        int o  = (2 * h2) * WW + 2 * w2;
        #pragma unroll
        for (int band = 0; band < 3; ++band) {
            const float* src = (band == 0) ? sLH : (band == 1) ? sHH : sHL;
            int sp = (band == 0) ? 0 : (band == 1) ? 1 : 2;
            int sq = (band == 0) ? 5 : (band == 1) ? 4 : 3;
            float a  = src[o]          * INV_SQRT2;
            float bb = src[o + 1]      * INV_SQRT2;
            float cc = src[o + WW]     * INV_SQRT2;
            float dd = src[o + WW + 1] * INV_SQRT2;
            size_t bp = ((size_t)bid * 6 + sp) * P2 + p;
            size_t bq = ((size_t)bid * 6 + sq) * P2 + p;
            g_xh[0][bp] = a - dd;
            g_xh[1][bp] = bb + cc;
            g_xh[0][bq] = a + dd;
            g_xh[1][bq] = bb - cc;
        }
    }
}

// ---------------- K3a: channel mixing ----------------
__global__ void __launch_bounds__(256, 2) k_chmix() {
    __shared__ float4 scw[2][1024];
    __shared__ float2 scb[2][64];
    int tid = threadIdx.x;
    #pragma unroll
    for (int i = 0; i < 4; ++i) {
        scw[0][tid + 256 * i] = g_cwq4[0][tid + 256 * i];
        scw[1][tid + 256 * i] = g_cwq4[1][tid + 256 * i];
    }
    if (tid < 64) { scb[0][tid] = g_cbq[0][tid]; scb[1][tid] = g_cbq[1][tid]; }
    __syncthreads();

    unsigned w0a = (unsigned)__cvta_generic_to_shared(&scw[0][0]);
    unsigned w1a = (unsigned)__cvta_generic_to_shared(&scw[1][0]);
    unsigned b0a = (unsigned)__cvta_generic_to_shared(&scb[0][0]);
    unsigned b1a = (unsigned)__cvta_generic_to_shared(&scb[1][0]);

    int item = blockIdx.x * 256 + tid;
    int b = item / 1176, rem = item - b * 1176;
    int s = rem / 196, p = rem - s * 196;
    float* Xr = g_xh[0];
    float* Xi = g_xh[1];
    size_t base = ((size_t)b * 384 + s) * 196 + p;

    for (int n = 0; n < 4; ++n) {
        u64 Xp[16], Xq[16];
        #pragma unroll
        for (int d = 0; d < 16; ++d) {
            float r = Xr[base + (size_t)(n * 16 + d) * 1176];
            float m = Xi[base + (size_t)(n * 16 + d) * 1176];
            Xp[d] = pk2(r, r);
            Xq[d] = pk2(m, m);
        }
        float mr[16], mi[16];
        #pragma unroll
        for (int k = 0; k < 16; ++k) {
            u64 A = lds1u64(b0a + (unsigned)(n * 16 + k) * 8);
            unsigned wa = w0a + (unsigned)((n * 16 + k) * 16) * 16;
            #pragma unroll
            for (int d = 0; d < 16; ++d) {
                u64 W0, W1; lds2u64(W0, W1, wa + d * 16);
                ffma2(A, Xp[d], W0);
                ffma2(A, Xq[d], W1);
            }
            float ar, ai; upk2(A, ar, ai);
            mr[k] = fmaxf(ar, 0.f);
            mi[k] = fmaxf(ai, 0.f);
        }
        #pragma unroll
        for (int d = 0; d < 16; ++d) { Xp[d] = pk2(mr[d], mr[d]); Xq[d] = pk2(mi[d], mi[d]); }
        #pragma unroll
        for (int k = 0; k < 16; ++k) {
            u64 A = lds1u64(b1a + (unsigned)(n * 16 + k) * 8);
            unsigned wa = w1a + (unsigned)((n * 16 + k) * 16) * 16;
            #pragma unroll
            for (int d = 0; d < 16; ++d) {
                u64 W0, W1; lds2u64(W0, W1, wa + d * 16);
                ffma2(A, Xp[d], W0);
                ffma2(A, Xq[d], W1);
            }
            float ar, ai; upk2(A, ar, ai);
            Xr[base + (size_t)(n * 16 + k) * 1176] = ar;
            Xi[base + (size_t)(n * 16 + k) * 1176] = ai;
        }
    }
}

// ---------------- K3b: token mixing ----------------
__global__ void __launch_bounds__(128, 4) k_token() {
    __shared__ float4 stw[2][196];
    __shared__ float2 stb[2][14];
    int tid = threadIdx.x;
    int b  = blockIdx.x / 42;
    int r  = blockIdx.x % 42;
    int h2 = r / 3;
    int gs = r % 3;
    for (int i = tid; i < 196; i += 128) {
        stw[0][i] = g_twq4[0][h2 * 196 + i];
        stw[1][i] = g_twq4[1][h2 * 196 + i];
    }
    if (tid < 14) { stb[0][tid] = g_tbq[0][h2 * 14 + tid]; stb[1][tid] = g_tbq[1][h2 * 14 + tid]; }
    __syncthreads();

    unsigned w0a = (unsigned)__cvta_generic_to_shared(&stw[0][0]);
    unsigned w1a = (unsigned)__cvta_generic_to_shared(&stw[1][0]);
    unsigned b0a = (unsigned)__cvta_generic_to_shared(&stb[0][0]);
    unsigned b1a = (unsigned)__cvta_generic_to_shared(&stb[1][0]);

    int s = gs * 2 + (tid >> 6);
    int c = tid & 63;
    size_t base = ((size_t)(b * 64 + c) * 6 + s) * 196 + h2 * 14;
    float2* Rp = (float2*)(g_xh[0] + base);
    float2* Ip = (float2*)(g_xh[1] + base);

    u64 Xp[14], Xq[14];
    #pragma unroll
    for (int j = 0; j < 7; ++j) {
        float2 v = Rp[j];
        Xp[2 * j]     = pk2(v.x, v.x);
        Xp[2 * j + 1] = pk2(v.y, v.y);
        float2 w = Ip[j];
        Xq[2 * j]     = pk2(w.x, w.x);
        Xq[2 * j + 1] = pk2(w.y, w.y);
    }
    float mr[14], mi[14];
    #pragma unroll
    for (int k = 0; k < 14; ++k) {
        u64 A = lds1u64(b0a + (unsigned)k * 8);
        unsigned wa = w0a + (unsigned)(k * 14) * 16;
        #pragma unroll
        for (int d = 0; d < 14; ++d) {
            u64 W0, W1; lds2u64(W0, W1, wa + d * 16);
            ffma2(A, Xp[d], W0);
            ffma2(A, Xq[d], W1);
        }
        float ar, ai; upk2(A, ar, ai);
        mr[k] = fmaxf(ar, 0.f);
        mi[k] = fmaxf(ai, 0.f);
    }
    #pragma unroll
    for (int d = 0; d < 14; ++d) { Xp[d] = pk2(mr[d], mr[d]); Xq[d] = pk2(mi[d], mi[d]); }
    float outr[14], outi[14];
    #pragma unroll
    for (int k = 0; k < 14; ++k) {
        u64 A = lds1u64(b1a + (unsigned)k * 8);
        unsigned wa = w1a + (unsigned)(k * 14) * 16;
        #pragma unroll
        for (int d = 0; d < 14; ++d) {
            u64 W0, W1; lds2u64(W0, W1, wa + d * 16);
            ffma2(A, Xp[d], W0);
            ffma2(A, Xq[d], W1);
        }
        upk2(A, outr[k], outi[k]);
    }
    #pragma unroll
    for (int j = 0; j < 7; ++j) {
        Rp[j] = make_float2(outr[2 * j], outr[2 * j + 1]);
        Ip[j] = make_float2(outi[2 * j], outi[2 * j + 1]);
    }
}

// ---------------- K4: inverse DTCWT (strip-of-4, register windows) ----------------
__global__ void __launch_bounds__(224, 2) k_inv() {
    __shared__ float sLLT[WW][CP];     // transposed padded (pad in h)
    __shared__ float sLHT[WW][CP];
    __shared__ float sHLT[WW][CP];
    __shared__ float sHHT[WW][CP];
    __shared__ float sLo [HH][CP];     // row-major padded (pad in w)
    __shared__ float sHi [HH][CP];

    int bid = blockIdx.x;
    int tid = threadIdx.x;

    if (tid < 196) {
        float4 v = *(const float4*)(g_ll + (size_t)bid * HW + tid * 4);
        int h = (tid * 4) / 28, w = (tid * 4) % 28;
        sLLT[w][9 + h]     = v.x;
        sLLT[w + 1][9 + h] = v.y;
        sLLT[w + 2][9 + h] = v.z;
        sLLT[w + 3][9 + h] = v.w;
    }

    if (tid < 196) {   // c2q -> transposed arrays
        int p = tid, h2 = p / 14, w2 = p - h2 * 14;
        size_t base = (size_t)bid * 6 * P2;
        int hr = 9 + 2 * h2, wc = 2 * w2;
        #pragma unroll
        for (int band = 0; band < 3; ++band) {
            int sa = (band == 0) ? 0 : (band == 1) ? 2 : 1;   // lh:(0,5) hl:(2,3) hh:(1,4)
            int sb = (band == 0) ? 5 : (band == 1) ? 3 : 4;
            float ra = g_xh[0][base + sa * P2 + p], ia = g_xh[1][base + sa * P2 + p];
            float rb = g_xh[0][base + sb * P2 + p], ib = g_xh[1][base + sb * P2 + p];
            float (*dst)[CP] = (band == 0) ? sLHT : (band == 1) ? sHLT : sHHT;
            dst[wc][hr]         = (ra + rb) * INV_SQRT2;
            dst[wc + 1][hr]     = (ia + ib) * INV_SQRT2;
            dst[wc][hr + 1]     = (ia - ib) * INV_SQRT2;
            dst[wc + 1][hr + 1] = (rb - ra) * INV_SQRT2;
        }
    }
    __syncthreads();
    for (int i = tid; i < 28 * 9; i += 224) {
        int w = i / 9, j = i % 9;
        sLLT[w][8 - j] = sLLT[w][9 + j];  sLLT[w][37 + j] = sLLT[w][36 - j];
        sLHT[w][8 - j] = sLHT[w][9 + j];  sLHT[w][37 + j] = sLHT[w][36 - j];
        sHLT[w][8 - j] = sHLT[w][9 + j];  sHLT[w][37 + j] = sHLT[w][36 - j];
        sHHT[w][8 - j] = sHHT[w][9 + j];  sHHT[w][37 + j] = sHHT[w][36 - j];
    }
    __syncthreads();

    // column filters: lo = g0(ll)+g1(lh), hi = g0(hl)+g1(hh)
    if (tid < 196) {
        int w = tid % 28, h0 = (tid / 28) * 4;
        {
            float A[22], B[22];
            #pragma unroll
            for (int j = 0; j < 22; ++j) A[j] = sLLT[w][h0 + j];
            #pragma unroll
            for (int j = 0; j < 22; ++j) B[j] = sLHT[w][h0 + j];
            #pragma unroll
            for (int t = 0; t < 4; ++t) {
                float lo = 0.f;
                #pragma unroll
                for (int j = 0; j < 19; ++j) lo = fmaf(A[t + j], kG0[j], lo);
                #pragma unroll
                for (int j = 0; j < 13; ++j) lo = fmaf(B[t + 3 + j], kG1[j], lo);
                sLo[h0 + t][9 + w] = lo;
            }
        }
        {
            float A[22], B[22];
            #pragma unroll
            for (int j = 0; j < 22; ++j) A[j] = sHLT[w][h0 + j];
            #pragma unroll
            for (int j = 0; j < 22; ++j) B[j] = sHHT[w][h0 + j];
            #pragma unroll
            for (int t = 0; t < 4; ++t) {
                float hi = 0.f;
                #pragma unroll
                for (int j = 0; j < 19; ++j) hi = fmaf(A[t + j], kG0[j], hi);
                #pragma unroll
                for (int j = 0; j < 13; ++j) hi = fmaf(B[t + 3 + j], kG1[j], hi);
                sHi[h0 + t][9 + w] = hi;
            }
        }
    }
    __syncthreads();
    for (int i = tid; i < 28 * 9; i += 224) {
        int h = i / 9, j = i % 9;
        sLo[h][8 - j] = sLo[h][9 + j];  sLo[h][37 + j] = sLo[h][36 - j];
        sHi[h][8 - j] = sHi[h][9 + j];  sHi[h][37 + j] = sHi[h][36 - j];
    }
    __syncthreads();

    // row filters
    if (tid < 196) {
        int h = tid % 28, w0 = (tid / 28) * 4;
        float X[22], Y[22];
        #pragma unroll
        for (int j = 0; j < 22; ++j) X[j] = sLo[h][w0 + j];
        #pragma unroll
        for (int j = 0; j < 22; ++j) Y[j] = sHi[h][w0 + j];
        float4 v;
        float o[4];
        #pragma unroll
        for (int t = 0; t < 4; ++t) {
            float r = 0.f;
            #pragma unroll
            for (int j = 0; j < 19; ++j) r = fmaf(X[t + j], kG0[j], r);
            #pragma unroll
            for (int j = 0; j < 13; ++j) r = fmaf(Y[t + 3 + j], kG1[j], r);
            o[t] = r;
        }
        v.x = o[0]; v.y = o[1]; v.z = o[2]; v.w = o[3];
        *(float4*)(g_img + (size_t)bid * HW + h * 28 + w0) = v;
    }
}

// ---------------- K5: transpose g_img -> out[:, :, 64:128] ----------------
__global__ void k_transpose_out(float* __restrict__ out) {
    __shared__ float t[56][65];
    int b   = blockIdx.x / 14;
    int hw0 = (blockIdx.x % 14) * 56;
    #pragma unroll
    for (int it = 0; it < 14; ++it) {
        int idx = it * 256 + threadIdx.x;
        int i = idx % 56, c = idx / 56;
        t[i][c] = g_img[((size_t)b * CH + c) * HW + hw0 + i];
    }
    __syncthreads();
    #pragma unroll
    for (int it = 0; it < 14; ++it) {
        int idx = it * 256 + threadIdx.x;
        int i = idx >> 6, c = idx & 63;
        out[((size_t)b * HW + hw0 + i) * NC + CH + c] = t[i][c];
    }
}

extern "C" void kernel_launch(void* const* d_in, const int* in_sizes, int n_in,
                              void* d_out, int out_size) {
    const float* x      = (const float*)d_in[0];
    const float* conv_w = (const float*)d_in[1];
    const float* conv_b = (const float*)d_in[2];
    const float* w_ll   = (const float*)d_in[3];
    const float* w_lh1  = (const float*)d_in[4];
    const float* w_lh2  = (const float*)d_in[5];
    const float* b_lh1  = (const float*)d_in[6];
    const float* b_lh2  = (const float*)d_in[7];
    const float* w_t1   = (const float*)d_in[8];
    const float* w_t2   = (const float*)d_in[9];
    const float* b_t1   = (const float*)d_in[10];
    const float* b_t2   = (const float*)d_in[11];
    float* out = (float*)d_out;

    k_pack<<<11, 256>>>(w_lh1, w_lh2, b_lh1, b_lh2, w_t1, w_t2, b_t1, b_t2);
    k_transpose_in<<<BB * 14, 256>>>(x);
    k_dwconv<<<BB * HW / 4, 256>>>(x, conv_w, conv_b, out);
    k_fwd<<<BB * CH, 224>>>(w_ll);
    k_chmix<<<1176, 256>>>();
    k_token<<<BB * 14 * 3, 128>>>();
    k_inv<<<BB * CH, 224>>>();
    k_transpose_out<<<BB * 14, 256>>>(out);
}